// round 13
// baseline (speedup 1.0000x reference)
#include <cuda_runtime.h>
#include <cstdint>

// Shapes fixed by the problem: B=4, T=2048, D=768 -> E=2*D=1536, H=256.
#define B_DIM 4
#define T_DIM 2048
#define E_DIM 1536
#define H_DIM 256

#define NTHREADS   384                     // one thread per float4 column
#define N_BLOCKS   256                     // single wave at 2 blocks/SM
#define BLK_PER_B  (N_BLOCKS / B_DIM)      // 64
#define ROWS_PB    (T_DIM / BLK_PER_B)     // 32 rows per block
#define ROW_BYTES  (E_DIM * 4)             // 6144
#define G_ROWS     8                       // rows per cp.async group
#define G_BYTES    (G_ROWS * ROW_BYTES)    // 49152
#define N_GROUPS   (ROWS_PB / G_ROWS)      // 4
#define SMEM_BYTES (2 * G_BYTES)           // 96 KB, 2-stage ring
#define N_TAIL     64
#define D_CHUNK    (E_DIM / N_TAIL)        // 24

// Scratch (__device__ globals; allocation-free rule). g_part / g_hpart are
// FULLY overwritten every call -> no reset. Counters reset by last arriver.
__device__ float             g_part[BLK_PER_B][B_DIM * E_DIM];  // 1.5 MB
__device__ float             g_hpart[N_TAIL][B_DIM][H_DIM];
__device__ volatile unsigned g_c1;
__device__ unsigned          g_c2;

__device__ __forceinline__ void cpasync16(uint32_t dst, const char* src) {
    asm volatile("cp.async.cg.shared.global [%0], [%1], 16;"
                 :: "r"(dst), "l"(src) : "memory");
}
__device__ __forceinline__ void cp_commit() {
    asm volatile("cp.async.commit_group;" ::: "memory");
}
template <int N>
__device__ __forceinline__ void cp_wait() {
    asm volatile("cp.async.wait_group %0;" :: "n"(N) : "memory");
}

// Issue one 8-row group: thread t copies bytes [t*16, t*16+16) of each row.
__device__ __forceinline__ void issue_group(uint32_t s_dst, const char* g_src,
                                            int toff) {
#pragma unroll
    for (int k = 0; k < G_ROWS; k++)
        cpasync16(s_dst + k * ROW_BYTES + toff, g_src + k * ROW_BYTES + toff);
    cp_commit();
}
// Consume one group: thread t reads back exactly the bytes it copied.
__device__ __forceinline__ void consume_group(uint32_t s_src, int toff,
                                              float4& acc) {
#pragma unroll
    for (int k = 0; k < G_ROWS; k++) {
        float4 v;
        asm volatile("ld.shared.v4.f32 {%0,%1,%2,%3}, [%4];"
                     : "=f"(v.x), "=f"(v.y), "=f"(v.z), "=f"(v.w)
                     : "r"(s_src + k * ROW_BYTES + toff));
        acc.x += v.x; acc.y += v.y; acc.z += v.z; acc.w += v.w;
    }
}

__global__ void __launch_bounds__(NTHREADS, 2)
curiosity_fused(const float* __restrict__ x,
                const float* __restrict__ W1,
                const float* __restrict__ b1,
                const float* __restrict__ W2,
                const float* __restrict__ b2,
                float* __restrict__ out, int out_size) {
    extern __shared__ __align__(16) char smem[];
    const int tid  = threadIdx.x;
    const int bid  = blockIdx.x;
    const int toff = tid * 16;

    // ---------------- Phase 1: cp.async-pipelined column sum ---------------
    // Per-THREAD pipeline, zero block syncs: in-flight data lives in the
    // L1/smem queue, not registers, so MLP is not RF-bound.
    {
        const int b  = bid / BLK_PER_B;
        const int c  = bid % BLK_PER_B;
        const char* src = (const char*)x
                        + (size_t)(b * T_DIM + c * ROWS_PB) * ROW_BYTES;
        const uint32_t s0 = (uint32_t)__cvta_generic_to_shared(smem);
        const uint32_t s1 = s0 + G_BYTES;

        issue_group(s0, src + 0 * (size_t)G_BYTES, toff);
        issue_group(s1, src + 1 * (size_t)G_BYTES, toff);

        float4 acc = make_float4(0.f, 0.f, 0.f, 0.f);

        cp_wait<1>();                          // group 0 landed
        consume_group(s0, toff, acc);
        issue_group(s0, src + 2 * (size_t)G_BYTES, toff);

        cp_wait<1>();                          // group 1 landed
        consume_group(s1, toff, acc);
        issue_group(s1, src + 3 * (size_t)G_BYTES, toff);

        cp_wait<1>();                          // group 2 landed
        consume_group(s0, toff, acc);

        cp_wait<0>();                          // group 3 landed
        consume_group(s1, toff, acc);

        // Plain store into this block's own partial slot (no contention).
        reinterpret_cast<float4*>(&g_part[c][b * E_DIM])[tid] = acc;

        __syncthreads();                       // all partials stored
        if (tid == 0) {
            __threadfence();                   // release partials
            atomicAdd((unsigned*)&g_c1, 1u);
        }
    }

    // 192 non-tail blocks exit immediately.
    if (bid >= N_TAIL) return;

    // ---------------- Phase 2: GEMV1 tail (blocks 0..63) -------------------
    __shared__ float s[B_DIM][D_CHUNK];
    const int j  = tid;                        // hidden index (first 256 thr)
    const int d0 = bid * D_CHUNK;

    // Preload W1 chunk into registers BEFORE spinning (overlaps the stream).
    float w[D_CHUNK];
    if (j < H_DIM) {
#pragma unroll
        for (int dd = 0; dd < D_CHUNK; dd++)
            w[dd] = W1[(size_t)(d0 + dd) * H_DIM + j];
    }

    if (tid == 0) {
        while (g_c1 < N_BLOCKS) { }            // volatile poll
        __threadfence();                       // acquire
    }
    __syncthreads();

    // Reduce the 64 row-chunk partials for this (b, d) slice into means.
    for (int i = tid; i < B_DIM * D_CHUNK; i += NTHREADS) {
        int b = i / D_CHUNK, dd = i % D_CHUNK;
        int idx = b * E_DIM + d0 + dd;
        float cs = 0.f;
#pragma unroll 4
        for (int p = 0; p < BLK_PER_B; p++) cs += g_part[p][idx];
        s[b][dd] = cs * (1.0f / (float)T_DIM);
    }
    __syncthreads();

    if (j < H_DIM) {
        float a0 = 0.f, a1 = 0.f, a2 = 0.f, a3 = 0.f;
#pragma unroll
        for (int dd = 0; dd < D_CHUNK; dd++) {
            float ww = w[dd];
            a0 = fmaf(s[0][dd], ww, a0);
            a1 = fmaf(s[1][dd], ww, a1);
            a2 = fmaf(s[2][dd], ww, a2);
            a3 = fmaf(s[3][dd], ww, a3);
        }
        g_hpart[bid][0][j] = a0;
        g_hpart[bid][1][j] = a1;
        g_hpart[bid][2][j] = a2;
        g_hpart[bid][3][j] = a3;
    }

    // ---------------- Phase 3: epilogue in the LAST-arriving tail block ----
    __syncthreads();
    __shared__ unsigned s_last;
    if (tid == 0) {
        __threadfence();                       // release hidden partials
        s_last = (atomicAdd(&g_c2, 1u) == N_TAIL - 1u) ? 1u : 0u;
    }
    __syncthreads();
    if (!s_last) return;

    if (tid == 0) __threadfence();             // acquire all hidden partials
    __syncthreads();

    __shared__ float red[B_DIM][8];
    if (j < H_DIM) {
        const int lane = j & 31, warp = j >> 5;
        float w2 = W2[j];
        float bb = b1[j];
        float v[B_DIM];
#pragma unroll
        for (int b = 0; b < B_DIM; b++) {
            float h = bb;
#pragma unroll 8
            for (int p = 0; p < N_TAIL; p++) h += g_hpart[p][b][j];
            v[b] = fmaxf(h, 0.0f) * w2;
        }
#pragma unroll
        for (int off = 16; off > 0; off >>= 1)
#pragma unroll
            for (int b = 0; b < B_DIM; b++)
                v[b] += __shfl_down_sync(0xffffffffu, v[b], off);
        if (lane == 0)
#pragma unroll
            for (int b = 0; b < B_DIM; b++) red[b][warp] = v[b];
    }
    __syncthreads();

    if (tid < B_DIM && tid < out_size) {
        float sm = 0.f;
#pragma unroll
        for (int w8 = 0; w8 < 8; w8++) sm += red[tid][w8];
        out[tid] = sm + b2[0];
    }
    // best_action_idx slot: argmax over 32 bit-identical entropies == 0
    // always (int 0 == float 0.0 bit pattern). Zero-fill the rest.
    for (int i = B_DIM + tid; i < out_size; i += NTHREADS)
        out[i] = 0.0f;

    __syncthreads();
    if (tid == 0) { g_c2 = 0u; g_c1 = 0u; __threadfence(); }
}

extern "C" void kernel_launch(void* const* d_in, const int* in_sizes, int n_in,
                              void* d_out, int out_size) {
    const float* x  = (const float*)d_in[0];
    const float* W1 = (const float*)d_in[1];
    const float* b1 = (const float*)d_in[2];
    const float* W2 = (const float*)d_in[3];
    const float* b2 = (const float*)d_in[4];
    float* out = (float*)d_out;

    static bool attr_done = false;
    if (!attr_done) {
        cudaFuncSetAttribute(curiosity_fused,
                             cudaFuncAttributeMaxDynamicSharedMemorySize,
                             SMEM_BYTES);
        attr_done = true;
    }
    curiosity_fused<<<N_BLOCKS, NTHREADS, SMEM_BYTES>>>(
        x, W1, b1, W2, b2, out, out_size);
}

// round 14
// speedup vs baseline: 1.3034x; 1.3034x over previous
#include <cuda_runtime.h>

// Shapes fixed by the problem: B=4, T=2048, D=768 -> E=2*D=1536, H=256.
#define B_DIM 4
#define T_DIM 2048
#define E_DIM 1536
#define H_DIM 256

#define NT_CHUNKS 64
#define T_CHUNK   (T_DIM / NT_CHUNKS)      // 32
#define COLS4     (E_DIM / 4)              // 384 float4 per (b,t) row
#define CB_CHUNKS 6                        // 6 * 256 = 1536 = B*COLS4
#define N_BLOCKS  (CB_CHUNKS * NT_CHUNKS)  // 384
#define N_TAIL    16
#define D_CHUNK   (E_DIM / N_TAIL)         // 96

// Scratch: __device__ globals (allocation-free rule).
// g_part and g_hpart are FULLY overwritten every call (plain stores) -> no
// reset needed. Only the two counters are reset by the last-arriving block.
__device__ float             g_part[NT_CHUNKS][B_DIM * E_DIM];  // 1.5 MB
__device__ float             g_hpart[N_TAIL][B_DIM][H_DIM];
__device__ volatile unsigned g_c1;
__device__ unsigned          g_c2;

__global__ void __launch_bounds__(256, 2)
curiosity_fused(const float* __restrict__ x,
                const float* __restrict__ W1,
                const float* __restrict__ b1,
                const float* __restrict__ W2,
                const float* __restrict__ b2,
                float* __restrict__ out, int out_size) {
    const int tid = threadIdx.x;
    const int bid = blockIdx.x;

    // ---------------- Phase 1: column sum over T (all 384 blocks) ----------
    // EXACT R2/R10 body (unroll 8, launch_bounds(256,2) -> regs~128), but
    // with 32-row chunks: 296 blocks fill every SM x2, 88 spill as thirds.
    // Worst SM now streams 96 rows instead of 128 -> ~25% shorter phase 1.
    {
        int cb = bid % CB_CHUNKS;          // which 256-wide float4 col chunk
        int tb = bid / CB_CHUNKS;          // which T chunk (= partial slot)
        int gc = cb * 256 + tid;           // global (b, c4) in [0, 1536)
        int b  = gc / COLS4;
        int c4 = gc % COLS4;
        int t0 = tb * T_CHUNK;

        const float4* xp = reinterpret_cast<const float4*>(x)
                         + (size_t)(b * T_DIM + t0) * COLS4 + c4;

        float4 acc = make_float4(0.f, 0.f, 0.f, 0.f);
#pragma unroll 8
        for (int t = 0; t < T_CHUNK; t++) {
            float4 v = xp[(size_t)t * COLS4];
            acc.x += v.x; acc.y += v.y; acc.z += v.z; acc.w += v.w;
        }
        // Plain store: zero contention, no L2 atomic ALU serialization.
        reinterpret_cast<float4*>(&g_part[tb][0])[gc] = acc;

        __syncthreads();                   // all block stores issued
        if (tid == 0) {
            __threadfence();               // release partials before counter
            atomicAdd((unsigned*)&g_c1, 1u);
        }
    }

    // 368 non-tail blocks exit immediately.
    if (bid >= N_TAIL) return;

    // ---------------- Phase 2: GEMV1 tail (blocks 0..15) -------------------
    __shared__ float s[B_DIM][D_CHUNK];
    const int j  = tid;                    // hidden index, 256 threads = H
    const int d0 = bid * D_CHUNK;

    // Preload this block's W1 chunk into registers BEFORE spinning so the
    // loads overlap with the remaining colsum DRAM traffic (R2 trick).
    float w[D_CHUNK];
#pragma unroll
    for (int dd = 0; dd < D_CHUNK; dd++)
        w[dd] = W1[(size_t)(d0 + dd) * H_DIM + j];

    if (tid == 0) {
        while (g_c1 < N_BLOCKS) { }        // volatile poll
        __threadfence();                   // acquire
    }
    __syncthreads();

    // Reduce the 64 partials for this block's (b, d) slice into smem means.
    for (int i = tid; i < B_DIM * D_CHUNK; i += 256) {
        int b = i / D_CHUNK, dd = i % D_CHUNK;
        int idx = b * E_DIM + d0 + dd;
        float cs = 0.f;
#pragma unroll 8
        for (int p = 0; p < NT_CHUNKS; p++) cs += g_part[p][idx];
        s[b][dd] = cs * (1.0f / (float)T_DIM);
    }
    __syncthreads();

    float a0 = 0.f, a1 = 0.f, a2 = 0.f, a3 = 0.f;
#pragma unroll
    for (int dd = 0; dd < D_CHUNK; dd++) {
        float ww = w[dd];
        a0 = fmaf(s[0][dd], ww, a0);
        a1 = fmaf(s[1][dd], ww, a1);
        a2 = fmaf(s[2][dd], ww, a2);
        a3 = fmaf(s[3][dd], ww, a3);
    }
    g_hpart[bid][0][j] = a0;
    g_hpart[bid][1][j] = a1;
    g_hpart[bid][2][j] = a2;
    g_hpart[bid][3][j] = a3;

    // ---------------- Phase 3: epilogue in the LAST-arriving tail block ----
    __syncthreads();
    __shared__ unsigned s_last;
    if (tid == 0) {
        __threadfence();                   // release hidden partials
        s_last = (atomicAdd(&g_c2, 1u) == N_TAIL - 1u) ? 1u : 0u;
    }
    __syncthreads();
    if (!s_last) return;

    if (tid == 0) __threadfence();         // acquire all hidden partials
    __syncthreads();

    __shared__ float red[B_DIM][8];
    {
        const int lane = j & 31, warp = j >> 5;
        float w2 = W2[j];
        float bb = b1[j];
        float v[B_DIM];
#pragma unroll
        for (int b = 0; b < B_DIM; b++) {
            float h = bb;
#pragma unroll
            for (int p = 0; p < N_TAIL; p++) h += g_hpart[p][b][j];
            v[b] = fmaxf(h, 0.0f) * w2;
        }
#pragma unroll
        for (int off = 16; off > 0; off >>= 1)
#pragma unroll
            for (int b = 0; b < B_DIM; b++)
                v[b] += __shfl_down_sync(0xffffffffu, v[b], off);
        if (lane == 0)
#pragma unroll
            for (int b = 0; b < B_DIM; b++) red[b][warp] = v[b];
    }
    __syncthreads();

    if (tid < B_DIM && tid < out_size) {
        float sm = 0.f;
#pragma unroll
        for (int w8 = 0; w8 < 8; w8++) sm += red[tid][w8];
        out[tid] = sm + b2[0];
    }
    // best_action_idx slot: argmax over 32 bit-identical entropies == 0
    // always (int 0 == float 0.0 bit pattern). Zero-fill the rest.
    for (int i = B_DIM + tid; i < out_size; i += 256)
        out[i] = 0.0f;

    __syncthreads();
    if (tid == 0) { g_c2 = 0u; g_c1 = 0u; __threadfence(); }
}

extern "C" void kernel_launch(void* const* d_in, const int* in_sizes, int n_in,
                              void* d_out, int out_size) {
    const float* x  = (const float*)d_in[0];
    const float* W1 = (const float*)d_in[1];
    const float* b1 = (const float*)d_in[2];
    const float* W2 = (const float*)d_in[3];
    const float* b2 = (const float*)d_in[4];
    float* out = (float*)d_out;

    curiosity_fused<<<N_BLOCKS, 256>>>(x, W1, b1, W2, b2, out, out_size);
}

// round 16
// speedup vs baseline: 1.8348x; 1.4077x over previous
#include <cuda_runtime.h>

// Shapes fixed by the problem: B=4, T=2048, D=768 -> E=2*D=1536, H=256.
#define B_DIM 4
#define T_DIM 2048
#define E_DIM 1536
#define H_DIM 256

#define NT_CHUNKS 32
#define T_CHUNK   (T_DIM / NT_CHUNKS)      // 64
#define COLS4     (E_DIM / 4)              // 384 float4 per (b,t) row
#define CB_CHUNKS 6                        // 6 * 256 = 1536 = B*COLS4
#define N_BLOCKS  (CB_CHUNKS * NT_CHUNKS)  // 192
#define N_TAIL    16
#define D_CHUNK   (E_DIM / N_TAIL)         // 96

// Scratch: __device__ globals (allocation-free rule).
// g_part and g_hpart are FULLY overwritten every call (plain stores) -> no
// reset needed. Only the two counters are reset by the last-arriving block.
__device__ float             g_part[NT_CHUNKS][B_DIM * E_DIM];  // 786 KB
__device__ float             g_hpart[N_TAIL][B_DIM][H_DIM];
__device__ volatile unsigned g_c1;
__device__ unsigned          g_c2;

__global__ void __launch_bounds__(256, 2)
curiosity_fused(const float* __restrict__ x,
                const float* __restrict__ W1,
                const float* __restrict__ b1,
                const float* __restrict__ W2,
                const float* __restrict__ b2,
                float* __restrict__ out, int out_size) {
    const int tid = threadIdx.x;
    const int bid = blockIdx.x;

    // ---------------- Phase 1: column sum over T (all 192 blocks) ----------
    // Empirically-best shape (R2/R10): 256 threads x float4 col chunk,
    // 64 rows/block, regs~128 -> deep LDG batching. __ldcs = evict-first:
    // the 50 MB x stream is read once, so don't let it evict the partials
    // and W1 lines the tail re-reads from L2.
    {
        int cb = bid % CB_CHUNKS;          // which 256-wide float4 col chunk
        int tb = bid / CB_CHUNKS;          // which T chunk (= partial slot)
        int gc = cb * 256 + tid;           // global (b, c4) in [0, 1536)
        int b  = gc / COLS4;
        int c4 = gc % COLS4;
        int t0 = tb * T_CHUNK;

        const float4* xp = reinterpret_cast<const float4*>(x)
                         + (size_t)(b * T_DIM + t0) * COLS4 + c4;

        float4 acc = make_float4(0.f, 0.f, 0.f, 0.f);
#pragma unroll 8
        for (int t = 0; t < T_CHUNK; t++) {
            float4 v = __ldcs(xp + (size_t)t * COLS4);
            acc.x += v.x; acc.y += v.y; acc.z += v.z; acc.w += v.w;
        }
        // Plain store: zero contention, no L2 atomic ALU serialization.
        reinterpret_cast<float4*>(&g_part[tb][0])[gc] = acc;

        __syncthreads();                   // all block stores issued
        if (tid == 0) {
            __threadfence();               // release partials before counter
            atomicAdd((unsigned*)&g_c1, 1u);
        }
    }

    // 176 non-tail blocks exit immediately.
    if (bid >= N_TAIL) return;

    // ---------------- Phase 2: GEMV1 tail (blocks 0..15) -------------------
    __shared__ float s[B_DIM][D_CHUNK];
    const int j  = tid;                    // hidden index, 256 threads = H
    const int d0 = bid * D_CHUNK;

    // Preload this block's W1 chunk into registers BEFORE spinning so the
    // loads overlap with the remaining colsum DRAM traffic (R2 trick).
    float w[D_CHUNK];
#pragma unroll
    for (int dd = 0; dd < D_CHUNK; dd++)
        w[dd] = W1[(size_t)(d0 + dd) * H_DIM + j];

    if (tid == 0) {
        while (g_c1 < N_BLOCKS) { }        // volatile poll
        __threadfence();                   // acquire
    }
    __syncthreads();

    // Reduce the 32 partials for this block's (b, d) slice into smem means.
    // Loads hit L2 (freshly written, protected by the evict-first x stream).
    for (int i = tid; i < B_DIM * D_CHUNK; i += 256) {
        int b = i / D_CHUNK, dd = i % D_CHUNK;
        int idx = b * E_DIM + d0 + dd;
        float cs = 0.f;
#pragma unroll
        for (int p = 0; p < NT_CHUNKS; p++) cs += g_part[p][idx];
        s[b][dd] = cs * (1.0f / (float)T_DIM);
    }
    __syncthreads();

    float a0 = 0.f, a1 = 0.f, a2 = 0.f, a3 = 0.f;
#pragma unroll
    for (int dd = 0; dd < D_CHUNK; dd++) {
        float ww = w[dd];
        a0 = fmaf(s[0][dd], ww, a0);
        a1 = fmaf(s[1][dd], ww, a1);
        a2 = fmaf(s[2][dd], ww, a2);
        a3 = fmaf(s[3][dd], ww, a3);
    }
    g_hpart[bid][0][j] = a0;
    g_hpart[bid][1][j] = a1;
    g_hpart[bid][2][j] = a2;
    g_hpart[bid][3][j] = a3;

    // ---------------- Phase 3: epilogue in the LAST-arriving tail block ----
    __syncthreads();
    __shared__ unsigned s_last;
    if (tid == 0) {
        __threadfence();                   // release hidden partials
        s_last = (atomicAdd(&g_c2, 1u) == N_TAIL - 1u) ? 1u : 0u;
    }
    __syncthreads();
    if (!s_last) return;

    if (tid == 0) __threadfence();         // acquire all hidden partials
    __syncthreads();

    __shared__ float red[B_DIM][8];
    {
        const int lane = j & 31, warp = j >> 5;
        float w2 = W2[j];
        float bb = b1[j];
        float v[B_DIM];
#pragma unroll
        for (int b = 0; b < B_DIM; b++) {
            float h = bb;
#pragma unroll
            for (int p = 0; p < N_TAIL; p++) h += g_hpart[p][b][j];
            v[b] = fmaxf(h, 0.0f) * w2;
        }
#pragma unroll
        for (int off = 16; off > 0; off >>= 1)
#pragma unroll
            for (int b = 0; b < B_DIM; b++)
                v[b] += __shfl_down_sync(0xffffffffu, v[b], off);
        if (lane == 0)
#pragma unroll
            for (int b = 0; b < B_DIM; b++) red[b][warp] = v[b];
    }
    __syncthreads();

    if (tid < B_DIM && tid < out_size) {
        float sm = 0.f;
#pragma unroll
        for (int w8 = 0; w8 < 8; w8++) sm += red[tid][w8];
        out[tid] = sm + b2[0];
    }
    // best_action_idx slot: argmax over 32 bit-identical entropies == 0
    // always (int 0 == float 0.0 bit pattern). Zero-fill the rest.
    for (int i = B_DIM + tid; i < out_size; i += 256)
        out[i] = 0.0f;

    __syncthreads();
    if (tid == 0) { g_c2 = 0u; g_c1 = 0u; __threadfence(); }
}

extern "C" void kernel_launch(void* const* d_in, const int* in_sizes, int n_in,
                              void* d_out, int out_size) {
    const float* x  = (const float*)d_in[0];
    const float* W1 = (const float*)d_in[1];
    const float* b1 = (const float*)d_in[2];
    const float* W2 = (const float*)d_in[3];
    const float* b2 = (const float*)d_in[4];
    float* out = (float*)d_out;

    curiosity_fused<<<N_BLOCKS, 256>>>(x, W1, b1, W2, b2, out, out_size);
}